// round 1
// baseline (speedup 1.0000x reference)
#include <cuda_runtime.h>
#include <cuda_bf16.h>
#include <math.h>

#define BSZ     8
#define QL      16
#define TOK     128          // BSZ*QL
#define DIM     4096
#define NQH     32
#define NKV     8
#define HD      128
#define REP     4
#define MAXSEQ  4096
#define STARTP  4080         // MAX_SEQ - Q_LEN
#define KVLEN   4096
#define QKV_N   6144         // 4096 q + 1024 k + 1024 v

// ---------------- scratch (device globals; no allocation allowed) ----------
__device__ float g_qkv[TOK * QKV_N];               // 3 MB   q|k|v per token
__device__ float g_scores[BSZ * NKV * 64 * KVLEN]; // 64 MB  (b,g, qr=r*16+s, l)
__device__ float g_att[TOK * DIM];                 // 2 MB   attention output

// ---------------- generic 64x128 fp32 GEMM tile (K multiple of 32) ---------
// C[64 x 128] = A[64 x K] @ B[K x 128] + bias ; 256 threads, 4x8 per thread.
__device__ __forceinline__ void gemm_64x128(
    const float* __restrict__ A, int lda,
    const float* __restrict__ B, int ldb,
    const float* __restrict__ bias,
    float* __restrict__ C, int ldc, int K)
{
    __shared__ float As[32][64];    // transposed: [k][m]
    __shared__ float Bs[32][128];   // natural:    [k][n]

    float acc[4][8];
#pragma unroll
    for (int i = 0; i < 4; i++)
#pragma unroll
        for (int j = 0; j < 8; j++) acc[i][j] = 0.f;

    const int tid = threadIdx.x;
    const int tm  = (tid >> 4) << 2;   // 0..60
    const int tn  = (tid & 15) << 3;   // 0..120

    for (int k0 = 0; k0 < K; k0 += 32) {
#pragma unroll
        for (int i = 0; i < 2; i++) {           // A tile: 64x32 = 512 float4
            int idx = tid + i * 256;
            int m   = idx >> 3;
            int kk  = (idx & 7) << 2;
            float4 a = *(const float4*)(A + (size_t)m * lda + k0 + kk);
            As[kk + 0][m] = a.x; As[kk + 1][m] = a.y;
            As[kk + 2][m] = a.z; As[kk + 3][m] = a.w;
        }
#pragma unroll
        for (int i = 0; i < 4; i++) {           // B tile: 32x128 = 1024 float4
            int idx = tid + i * 256;
            int kk  = idx >> 5;
            int n   = (idx & 31) << 2;
            *(float4*)(&Bs[kk][n]) = *(const float4*)(B + (size_t)(k0 + kk) * ldb + n);
        }
        __syncthreads();
#pragma unroll
        for (int kk = 0; kk < 32; kk++) {
            float4 a4 = *(const float4*)(&As[kk][tm]);
            float4 b0 = *(const float4*)(&Bs[kk][tn]);
            float4 b1 = *(const float4*)(&Bs[kk][tn + 4]);
            float a[4] = {a4.x, a4.y, a4.z, a4.w};
            float b[8] = {b0.x, b0.y, b0.z, b0.w, b1.x, b1.y, b1.z, b1.w};
#pragma unroll
            for (int i = 0; i < 4; i++)
#pragma unroll
                for (int j = 0; j < 8; j++)
                    acc[i][j] = fmaf(a[i], b[j], acc[i][j]);
        }
        __syncthreads();
    }
#pragma unroll
    for (int i = 0; i < 4; i++) {
        float4 o0, o1;
        o0.x = acc[i][0] + bias[tn + 0];  o0.y = acc[i][1] + bias[tn + 1];
        o0.z = acc[i][2] + bias[tn + 2];  o0.w = acc[i][3] + bias[tn + 3];
        o1.x = acc[i][4] + bias[tn + 4];  o1.y = acc[i][5] + bias[tn + 5];
        o1.z = acc[i][6] + bias[tn + 6];  o1.w = acc[i][7] + bias[tn + 7];
        *(float4*)(C + (size_t)(tm + i) * ldc + tn)     = o0;
        *(float4*)(C + (size_t)(tm + i) * ldc + tn + 4) = o1;
    }
}

// ---------------- kernel 1: fused QKV projection ---------------------------
__global__ void qkv_gemm_kernel(
    const float* __restrict__ x,
    const float* __restrict__ Wq, const float* __restrict__ bq,
    const float* __restrict__ Wk, const float* __restrict__ bk,
    const float* __restrict__ Wv, const float* __restrict__ bv)
{
    int n0 = blockIdx.x * 128;
    int m0 = blockIdx.y * 64;
    const float *B, *bias; int ldb, col;
    if (n0 < 4096)      { B = Wq; bias = bq; ldb = 4096; col = n0; }
    else if (n0 < 5120) { B = Wk; bias = bk; ldb = 1024; col = n0 - 4096; }
    else                { B = Wv; bias = bv; ldb = 1024; col = n0 - 5120; }
    gemm_64x128(x + (size_t)m0 * DIM, DIM, B + col, ldb, bias + col,
                g_qkv + (size_t)m0 * QKV_N + n0, QKV_N, DIM);
}

// ---------------- kernel 2: scores = Q K^T * scale --------------------------
// grid: (KVLEN/128, BSZ*NKV). Block computes S[64 queries][128 kv].
__global__ void attn_scores_kernel(const float* __restrict__ k_cache)
{
    const int bg = blockIdx.y, b = bg >> 3, g = bg & 7;
    const int l0 = blockIdx.x * 128;

    __shared__ float Qs[32][64];    // [d][qr]
    __shared__ float Ks[32][128];   // [d][l]

    float acc[4][8];
#pragma unroll
    for (int i = 0; i < 4; i++)
#pragma unroll
        for (int j = 0; j < 8; j++) acc[i][j] = 0.f;

    const int tid = threadIdx.x;
    const int tm  = (tid >> 4) << 2;
    const int tn  = (tid & 15) << 3;
    const float* kc_base = k_cache + ((size_t)b * MAXSEQ * NKV + g) * HD;

    for (int d0 = 0; d0 < HD; d0 += 32) {
#pragma unroll
        for (int i = 0; i < 2; i++) {            // Q tile: 64 qr x 32 d
            int idx = tid + i * 256;
            int m   = idx >> 3;                  // qr
            int kk  = (idx & 7) << 2;
            int r = m >> 4, s = m & 15;
            float4 a = *(const float4*)(g_qkv + (size_t)(b * 16 + s) * QKV_N
                                        + (g * 4 + r) * HD + d0 + kk);
            Qs[kk + 0][m] = a.x; Qs[kk + 1][m] = a.y;
            Qs[kk + 2][m] = a.z; Qs[kk + 3][m] = a.w;
        }
#pragma unroll
        for (int i = 0; i < 4; i++) {            // K tile: 128 l x 32 d
            int idx = tid + i * 256;
            int l   = idx >> 3;
            int kk  = (idx & 7) << 2;
            int lg  = l0 + l;
            const float* src = (lg >= STARTP)
                ? (g_qkv + (size_t)(b * 16 + (lg - STARTP)) * QKV_N + 4096 + g * HD)
                : (kc_base + (size_t)lg * NKV * HD);
            float4 kv = *(const float4*)(src + d0 + kk);
            Ks[kk + 0][l] = kv.x; Ks[kk + 1][l] = kv.y;
            Ks[kk + 2][l] = kv.z; Ks[kk + 3][l] = kv.w;
        }
        __syncthreads();
#pragma unroll
        for (int kk = 0; kk < 32; kk++) {
            float4 a4 = *(const float4*)(&Qs[kk][tm]);
            float4 b0 = *(const float4*)(&Ks[kk][tn]);
            float4 b1 = *(const float4*)(&Ks[kk][tn + 4]);
            float a[4] = {a4.x, a4.y, a4.z, a4.w};
            float b[8] = {b0.x, b0.y, b0.z, b0.w, b1.x, b1.y, b1.z, b1.w};
#pragma unroll
            for (int i = 0; i < 4; i++)
#pragma unroll
                for (int j = 0; j < 8; j++)
                    acc[i][j] = fmaf(a[i], b[j], acc[i][j]);
        }
        __syncthreads();
    }
    const float scale = 0.08838834764831845f;    // 1/sqrt(128)
#pragma unroll
    for (int i = 0; i < 4; i++) {
        float* srow = g_scores + ((size_t)bg * 64 + (tm + i)) * KVLEN + l0 + tn;
        float4 o0 = {acc[i][0] * scale, acc[i][1] * scale, acc[i][2] * scale, acc[i][3] * scale};
        float4 o1 = {acc[i][4] * scale, acc[i][5] * scale, acc[i][6] * scale, acc[i][7] * scale};
        *(float4*)(srow)     = o0;
        *(float4*)(srow + 4) = o1;
    }
}

// ---------------- kernel 3: row softmax over 4096 ---------------------------
__global__ void softmax_kernel()
{
    float* p = g_scores + (size_t)blockIdx.x * KVLEN;
    __shared__ float buf[KVLEN];
    __shared__ float red[16];
    const int tid = threadIdx.x;

    float m = -1e30f;
    for (int i = tid * 4; i < KVLEN; i += 1024) {
        float4 v = *(const float4*)(p + i);
        *(float4*)(&buf[i]) = v;
        m = fmaxf(m, fmaxf(fmaxf(v.x, v.y), fmaxf(v.z, v.w)));
    }
#pragma unroll
    for (int o = 16; o; o >>= 1) m = fmaxf(m, __shfl_xor_sync(0xffffffffu, m, o));
    if ((tid & 31) == 0) red[tid >> 5] = m;
    __syncthreads();
    m = red[0];
#pragma unroll
    for (int w = 1; w < 8; w++) m = fmaxf(m, red[w]);

    float s = 0.f;
    for (int i = tid * 4; i < KVLEN; i += 1024) {
        float4 v = *(const float4*)(&buf[i]);
        v.x = __expf(v.x - m); v.y = __expf(v.y - m);
        v.z = __expf(v.z - m); v.w = __expf(v.w - m);
        *(float4*)(&buf[i]) = v;
        s += v.x + v.y + v.z + v.w;
    }
#pragma unroll
    for (int o = 16; o; o >>= 1) s += __shfl_xor_sync(0xffffffffu, s, o);
    if ((tid & 31) == 0) red[8 + (tid >> 5)] = s;
    __syncthreads();
    s = red[8];
#pragma unroll
    for (int w = 1; w < 8; w++) s += red[8 + w];
    float inv = 1.f / s;

    for (int i = tid * 4; i < KVLEN; i += 1024) {
        float4 v = *(const float4*)(&buf[i]);
        v.x *= inv; v.y *= inv; v.z *= inv; v.w *= inv;
        *(float4*)(p + i) = v;
    }
}

// ---------------- kernel 4: zero the attention accumulator ------------------
__global__ void zero_att_kernel()
{
    int i = (blockIdx.x * 256 + threadIdx.x) * 4;
    *(float4*)(g_att + i) = make_float4(0.f, 0.f, 0.f, 0.f);
}

// ---------------- kernel 5: O_part = P @ V (split-K over kv, atomic acc) ----
// grid: (16 splits, BSZ*NKV). Each block: 64 queries x 128 dims over 256 kv.
__global__ void attn_av_kernel(const float* __restrict__ v_cache)
{
    const int bg = blockIdx.y, b = bg >> 3, g = bg & 7;
    const int split = blockIdx.x;

    __shared__ float Ps[32][64];    // [l][qr]
    __shared__ float Vs[32][128];   // [l][d]

    float acc[4][8];
#pragma unroll
    for (int i = 0; i < 4; i++)
#pragma unroll
        for (int j = 0; j < 8; j++) acc[i][j] = 0.f;

    const int tid = threadIdx.x;
    const int tm  = (tid >> 4) << 2;
    const int tn  = (tid & 15) << 3;
    const float* vc_base = v_cache + ((size_t)b * MAXSEQ * NKV + g) * HD;

    for (int c = 0; c < 8; c++) {
        int lbase = split * 256 + c * 32;
#pragma unroll
        for (int i = 0; i < 2; i++) {            // P tile: 64 qr x 32 l
            int idx = tid + i * 256;
            int qr  = idx >> 3;
            int ll  = (idx & 7) << 2;
            float4 pv = *(const float4*)(g_scores + ((size_t)bg * 64 + qr) * KVLEN + lbase + ll);
            Ps[ll + 0][qr] = pv.x; Ps[ll + 1][qr] = pv.y;
            Ps[ll + 2][qr] = pv.z; Ps[ll + 3][qr] = pv.w;
        }
#pragma unroll
        for (int i = 0; i < 4; i++) {            // V tile: 32 l x 128 d
            int idx = tid + i * 256;
            int ll  = idx >> 5;
            int d   = (idx & 31) << 2;
            int lg  = lbase + ll;
            const float* src = (lg >= STARTP)
                ? (g_qkv + (size_t)(b * 16 + (lg - STARTP)) * QKV_N + 5120 + g * HD)
                : (vc_base + (size_t)lg * NKV * HD);
            *(float4*)(&Vs[ll][d]) = *(const float4*)(src + d);
        }
        __syncthreads();
#pragma unroll
        for (int kk = 0; kk < 32; kk++) {
            float4 a4 = *(const float4*)(&Ps[kk][tm]);
            float4 b0 = *(const float4*)(&Vs[kk][tn]);
            float4 b1 = *(const float4*)(&Vs[kk][tn + 4]);
            float a[4] = {a4.x, a4.y, a4.z, a4.w};
            float b[8] = {b0.x, b0.y, b0.z, b0.w, b1.x, b1.y, b1.z, b1.w};
#pragma unroll
            for (int i = 0; i < 4; i++)
#pragma unroll
                for (int j = 0; j < 8; j++)
                    acc[i][j] = fmaf(a[i], b[j], acc[i][j]);
        }
        __syncthreads();
    }
#pragma unroll
    for (int i = 0; i < 4; i++) {
        int qr = tm + i, r = qr >> 4, s = qr & 15;
        float* dst = g_att + (size_t)(b * 16 + s) * DIM + (g * 4 + r) * HD + tn;
#pragma unroll
        for (int j = 0; j < 8; j++) atomicAdd(dst + j, acc[i][j]);
    }
}

// ---------------- kernel 6: output projection -------------------------------
__global__ void out_gemm_kernel(const float* __restrict__ Wo,
                                const float* __restrict__ bo,
                                float* __restrict__ out)
{
    int n0 = blockIdx.x * 128;
    int m0 = blockIdx.y * 64;
    gemm_64x128(g_att + (size_t)m0 * DIM, DIM, Wo + n0, DIM, bo + n0,
                out + (size_t)m0 * DIM + n0, DIM, DIM);
}

// ---------------- launch -----------------------------------------------------
extern "C" void kernel_launch(void* const* d_in, const int* in_sizes, int n_in,
                              void* d_out, int out_size)
{
    const float* x  = (const float*)d_in[0];
    const float* kc = (const float*)d_in[1];
    const float* vc = (const float*)d_in[2];
    const float* Wq = (const float*)d_in[3];  const float* bq = (const float*)d_in[4];
    const float* Wk = (const float*)d_in[5];  const float* bk = (const float*)d_in[6];
    const float* Wv = (const float*)d_in[7];  const float* bv = (const float*)d_in[8];
    const float* Wo = (const float*)d_in[9];  const float* bo = (const float*)d_in[10];
    float* out = (float*)d_out;

    zero_att_kernel<<<512, 256>>>();
    qkv_gemm_kernel<<<dim3(48, 2), 256>>>(x, Wq, bq, Wk, bk, Wv, bv);
    attn_scores_kernel<<<dim3(KVLEN / 128, BSZ * NKV), 256>>>(kc);
    softmax_kernel<<<BSZ * NKV * 64, 256>>>();
    attn_av_kernel<<<dim3(16, BSZ * NKV), 256>>>(vc);
    out_gemm_kernel<<<dim3(DIM / 128, 2), 256>>>(Wo, bo, out);
}

// round 2
// speedup vs baseline: 1.5898x; 1.5898x over previous
#include <cuda_runtime.h>
#include <cuda_bf16.h>
#include <mma.h>
#include <math.h>

using namespace nvcuda;

#define BSZ     8
#define QL      16
#define TOK     128
#define DIM     4096
#define NKV     8
#define HD      128
#define MAXSEQ  4096
#define STARTP  4080
#define KVLEN   4096
#define QKV_N   6144
#define NBG     64            // BSZ*NKV
#define PV_SPLITS 8

// ---------------- scratch ----------------------------------------------------
__device__ float g_qkv[TOK * QKV_N];                    // 3 MB   raw qkv (no bias)
__device__ float g_scores[NBG * 64 * KVLEN];            // 64 MB
__device__ float g_pv[PV_SPLITS * NBG * 64 * HD];       // 16 MB  split-K partials
__device__ float g_att[TOK * DIM];                      // 2 MB

// ---------------- wmma inner step --------------------------------------------
// acc[2][2] covers a 32x32 warp tile. As row-major [64][LDA], Bs row-major [32][LDB].
template<int LDA, int LDB>
__device__ __forceinline__ void mma_rowB(
    const float* __restrict__ As, const float* __restrict__ Bs,
    wmma::fragment<wmma::accumulator, 16, 16, 8, float> (&acc)[2][2],
    int wr, int wc)
{
#pragma unroll
    for (int kk = 0; kk < 32; kk += 8) {
        wmma::fragment<wmma::matrix_a, 16, 16, 8, wmma::precision::tf32, wmma::row_major> a[2];
        wmma::fragment<wmma::matrix_b, 16, 16, 8, wmma::precision::tf32, wmma::row_major> b[2];
#pragma unroll
        for (int i = 0; i < 2; i++) {
            wmma::load_matrix_sync(a[i], As + (wr * 32 + i * 16) * LDA + kk, LDA);
#pragma unroll
            for (int t = 0; t < a[i].num_elements; t++)
                a[i].x[t] = wmma::__float_to_tf32(a[i].x[t]);
        }
#pragma unroll
        for (int j = 0; j < 2; j++) {
            wmma::load_matrix_sync(b[j], Bs + kk * LDB + wc * 32 + j * 16, LDB);
#pragma unroll
            for (int t = 0; t < b[j].num_elements; t++)
                b[j].x[t] = wmma::__float_to_tf32(b[j].x[t]);
        }
#pragma unroll
        for (int i = 0; i < 2; i++)
#pragma unroll
            for (int j = 0; j < 2; j++)
                wmma::mma_sync(acc[i][j], a[i], b[j], acc[i][j]);
    }
}

// B as col-major [n][LDB] (n rows of k-contiguous data) — used for scores (K^T).
template<int LDA, int LDB>
__device__ __forceinline__ void mma_colB(
    const float* __restrict__ As, const float* __restrict__ Bs,
    wmma::fragment<wmma::accumulator, 16, 16, 8, float> (&acc)[2][2],
    int wr, int wc)
{
#pragma unroll
    for (int kk = 0; kk < 32; kk += 8) {
        wmma::fragment<wmma::matrix_a, 16, 16, 8, wmma::precision::tf32, wmma::row_major> a[2];
        wmma::fragment<wmma::matrix_b, 16, 16, 8, wmma::precision::tf32, wmma::col_major> b[2];
#pragma unroll
        for (int i = 0; i < 2; i++) {
            wmma::load_matrix_sync(a[i], As + (wr * 32 + i * 16) * LDA + kk, LDA);
#pragma unroll
            for (int t = 0; t < a[i].num_elements; t++)
                a[i].x[t] = wmma::__float_to_tf32(a[i].x[t]);
        }
#pragma unroll
        for (int j = 0; j < 2; j++) {
            wmma::load_matrix_sync(b[j], Bs + (wc * 32 + j * 16) * LDB + kk, LDB);
#pragma unroll
            for (int t = 0; t < b[j].num_elements; t++)
                b[j].x[t] = wmma::__float_to_tf32(b[j].x[t]);
        }
#pragma unroll
        for (int i = 0; i < 2; i++)
#pragma unroll
            for (int j = 0; j < 2; j++)
                wmma::mma_sync(acc[i][j], a[i], b[j], acc[i][j]);
    }
}

// ---------------- kernel 1: QKV GEMM (raw, no bias) --------------------------
// grid (48, 2), 256 threads. Tile 64(m) x 128(n), K=4096.
__global__ void qkv_kernel(
    const float* __restrict__ x,
    const float* __restrict__ Wq, const float* __restrict__ Wk,
    const float* __restrict__ Wv)
{
    __shared__ float As[64 * 40];
    __shared__ float Bs[32 * 136];

    const int n0 = blockIdx.x * 128;
    const int m0 = blockIdx.y * 64;
    const float* B; int ldb, col;
    if (n0 < 4096)      { B = Wq; ldb = 4096; col = n0; }
    else if (n0 < 5120) { B = Wk; ldb = 1024; col = n0 - 4096; }
    else                { B = Wv; ldb = 1024; col = n0 - 5120; }

    const int tid = threadIdx.x;
    const int wid = tid >> 5, wr = wid >> 2, wc = wid & 3;

    wmma::fragment<wmma::accumulator, 16, 16, 8, float> acc[2][2];
#pragma unroll
    for (int i = 0; i < 2; i++)
#pragma unroll
        for (int j = 0; j < 2; j++) wmma::fill_fragment(acc[i][j], 0.0f);

    for (int k0 = 0; k0 < DIM; k0 += 32) {
#pragma unroll
        for (int i = 0; i < 2; i++) {
            int idx = tid + i * 256;
            int m = idx >> 3, k4 = (idx & 7) << 2;
            *(float4*)(As + m * 40 + k4) =
                *(const float4*)(x + (size_t)(m0 + m) * DIM + k0 + k4);
        }
#pragma unroll
        for (int i = 0; i < 4; i++) {
            int idx = tid + i * 256;
            int kk = idx >> 5, n4 = (idx & 31) << 2;
            *(float4*)(Bs + kk * 136 + n4) =
                *(const float4*)(B + (size_t)(k0 + kk) * ldb + col + n4);
        }
        __syncthreads();
        mma_rowB<40, 136>(As, Bs, acc, wr, wc);
        __syncthreads();
    }
#pragma unroll
    for (int i = 0; i < 2; i++)
#pragma unroll
        for (int j = 0; j < 2; j++)
            wmma::store_matrix_sync(
                g_qkv + (size_t)(m0 + wr * 32 + i * 16) * QKV_N + n0 + wc * 32 + j * 16,
                acc[i][j], QKV_N, wmma::mem_row_major);
}

// ---------------- kernel 2: scores = (Q+bq)*scale @ K^T ----------------------
// grid (32, 64): bx = l-tile(128), by = bg. 256 threads.
__global__ void scores_kernel(
    const float* __restrict__ k_cache,
    const float* __restrict__ bq, const float* __restrict__ bk)
{
    __shared__ float Qs[64 * 40];     // [qr][d-chunk]
    __shared__ float Ks[128 * 40];    // [l][d-chunk]  (col-major B)

    const int bg = blockIdx.y, b = bg >> 3, g = bg & 7;
    const int l0 = blockIdx.x * 128;
    const int tid = threadIdx.x;
    const int wid = tid >> 5, wr = wid >> 2, wc = wid & 3;
    const float scale = 0.08838834764831845f;

    wmma::fragment<wmma::accumulator, 16, 16, 8, float> acc[2][2];
#pragma unroll
    for (int i = 0; i < 2; i++)
#pragma unroll
        for (int j = 0; j < 2; j++) wmma::fill_fragment(acc[i][j], 0.0f);

    for (int d0 = 0; d0 < HD; d0 += 32) {
#pragma unroll
        for (int i = 0; i < 2; i++) {          // Q: 64 x 32
            int idx = tid + i * 256;
            int m = idx >> 3, d4 = (idx & 7) << 2;
            int r = m >> 4, s = m & 15;
            int hcol = (g * 4 + r) * HD + d0 + d4;
            float4 q = *(const float4*)(g_qkv + (size_t)(b * 16 + s) * QKV_N + hcol);
            float4 bb = *(const float4*)(bq + hcol);
            float4 o;
            o.x = (q.x + bb.x) * scale; o.y = (q.y + bb.y) * scale;
            o.z = (q.z + bb.z) * scale; o.w = (q.w + bb.w) * scale;
            *(float4*)(Qs + m * 40 + d4) = o;
        }
#pragma unroll
        for (int i = 0; i < 4; i++) {          // K: 128 x 32
            int idx = tid + i * 256;
            int l = idx >> 3, d4 = (idx & 7) << 2;
            int lg = l0 + l;
            float4 kv;
            if (lg >= STARTP) {
                kv = *(const float4*)(g_qkv + (size_t)(b * 16 + (lg - STARTP)) * QKV_N
                                      + 4096 + g * HD + d0 + d4);
                float4 bb = *(const float4*)(bk + g * HD + d0 + d4);
                kv.x += bb.x; kv.y += bb.y; kv.z += bb.z; kv.w += bb.w;
            } else {
                kv = *(const float4*)(k_cache + (((size_t)b * MAXSEQ + lg) * NKV + g) * HD
                                      + d0 + d4);
            }
            *(float4*)(Ks + l * 40 + d4) = kv;
        }
        __syncthreads();
        mma_colB<40, 40>(Qs, Ks, acc, wr, wc);
        __syncthreads();
    }
#pragma unroll
    for (int i = 0; i < 2; i++)
#pragma unroll
        for (int j = 0; j < 2; j++)
            wmma::store_matrix_sync(
                g_scores + (size_t)(bg * 64 + wr * 32 + i * 16) * KVLEN + l0 + wc * 32 + j * 16,
                acc[i][j], KVLEN, wmma::mem_row_major);
}

// ---------------- kernel 3: row softmax over 4096 -----------------------------
__global__ void softmax_kernel()
{
    float* p = g_scores + (size_t)blockIdx.x * KVLEN;
    __shared__ float buf[KVLEN];
    __shared__ float red[16];
    const int tid = threadIdx.x;

    float m = -1e30f;
    for (int i = tid * 4; i < KVLEN; i += 1024) {
        float4 v = *(const float4*)(p + i);
        *(float4*)(&buf[i]) = v;
        m = fmaxf(m, fmaxf(fmaxf(v.x, v.y), fmaxf(v.z, v.w)));
    }
#pragma unroll
    for (int o = 16; o; o >>= 1) m = fmaxf(m, __shfl_xor_sync(0xffffffffu, m, o));
    if ((tid & 31) == 0) red[tid >> 5] = m;
    __syncthreads();
    m = red[0];
#pragma unroll
    for (int w = 1; w < 8; w++) m = fmaxf(m, red[w]);

    float s = 0.f;
    for (int i = tid * 4; i < KVLEN; i += 1024) {
        float4 v = *(const float4*)(&buf[i]);
        v.x = __expf(v.x - m); v.y = __expf(v.y - m);
        v.z = __expf(v.z - m); v.w = __expf(v.w - m);
        *(float4*)(&buf[i]) = v;
        s += v.x + v.y + v.z + v.w;
    }
#pragma unroll
    for (int o = 16; o; o >>= 1) s += __shfl_xor_sync(0xffffffffu, s, o);
    if ((tid & 31) == 0) red[8 + (tid >> 5)] = s;
    __syncthreads();
    s = red[8];
#pragma unroll
    for (int w = 1; w < 8; w++) s += red[8 + w];
    float inv = 1.f / s;

    for (int i = tid * 4; i < KVLEN; i += 1024) {
        float4 v = *(const float4*)(&buf[i]);
        v.x *= inv; v.y *= inv; v.z *= inv; v.w *= inv;
        *(float4*)(p + i) = v;
    }
}

// ---------------- kernel 4: PV split-K ----------------------------------------
// grid (PV_SPLITS, 64): each block 64(qr) x 128(d) over 512 kv positions.
__global__ void pv_kernel(const float* __restrict__ v_cache,
                          const float* __restrict__ bv)
{
    __shared__ float As[64 * 40];     // P chunk [qr][l]
    __shared__ float Bs[32 * 136];    // V chunk [l][d]

    const int split = blockIdx.x;
    const int bg = blockIdx.y, b = bg >> 3, g = bg & 7;
    const int tid = threadIdx.x;
    const int wid = tid >> 5, wr = wid >> 2, wc = wid & 3;

    wmma::fragment<wmma::accumulator, 16, 16, 8, float> acc[2][2];
#pragma unroll
    for (int i = 0; i < 2; i++)
#pragma unroll
        for (int j = 0; j < 2; j++) wmma::fill_fragment(acc[i][j], 0.0f);

    for (int c = 0; c < 512 / 32; c++) {
        int lbase = split * 512 + c * 32;
#pragma unroll
        for (int i = 0; i < 2; i++) {          // P: 64 x 32
            int idx = tid + i * 256;
            int qr = idx >> 3, l4 = (idx & 7) << 2;
            *(float4*)(As + qr * 40 + l4) =
                *(const float4*)(g_scores + (size_t)(bg * 64 + qr) * KVLEN + lbase + l4);
        }
#pragma unroll
        for (int i = 0; i < 4; i++) {          // V: 32 x 128
            int idx = tid + i * 256;
            int kk = idx >> 5, n4 = (idx & 31) << 2;
            int lg = lbase + kk;
            float4 v;
            if (lg >= STARTP) {
                v = *(const float4*)(g_qkv + (size_t)(b * 16 + (lg - STARTP)) * QKV_N
                                     + 5120 + g * HD + n4);
                float4 bb = *(const float4*)(bv + g * HD + n4);
                v.x += bb.x; v.y += bb.y; v.z += bb.z; v.w += bb.w;
            } else {
                v = *(const float4*)(v_cache + (((size_t)b * MAXSEQ + lg) * NKV + g) * HD + n4);
            }
            *(float4*)(Bs + kk * 136 + n4) = v;
        }
        __syncthreads();
        mma_rowB<40, 136>(As, Bs, acc, wr, wc);
        __syncthreads();
    }
#pragma unroll
    for (int i = 0; i < 2; i++)
#pragma unroll
        for (int j = 0; j < 2; j++)
            wmma::store_matrix_sync(
                g_pv + ((size_t)split * NBG * 64 + bg * 64 + wr * 32 + i * 16) * HD
                     + wc * 32 + j * 16,
                acc[i][j], HD, wmma::mem_row_major);
}

// ---------------- kernel 5: reduce splits -> g_att (with head remap) ----------
__global__ void pv_reduce_kernel()
{
    int t = blockIdx.x * 256 + threadIdx.x;       // 131072 threads, one float4 each
    int row = t >> 5;                              // bg*64 + qr
    int c4  = (t & 31) << 2;
    float4 s = make_float4(0.f, 0.f, 0.f, 0.f);
#pragma unroll
    for (int sp = 0; sp < PV_SPLITS; sp++) {
        float4 v = *(const float4*)(g_pv + ((size_t)sp * NBG * 64 + row) * HD + c4);
        s.x += v.x; s.y += v.y; s.z += v.z; s.w += v.w;
    }
    int bg = row >> 6, qr = row & 63;
    int b = bg >> 3, g = bg & 7, r = qr >> 4, sq = qr & 15;
    *(float4*)(g_att + (size_t)(b * 16 + sq) * DIM + (g * 4 + r) * HD + c4) = s;
}

// ---------------- kernel 6: O projection (raw) ---------------------------------
// grid (32, 2): tile 64 x 128, K=4096.
__global__ void o_kernel(const float* __restrict__ Wo, float* __restrict__ out)
{
    __shared__ float As[64 * 40];
    __shared__ float Bs[32 * 136];

    const int n0 = blockIdx.x * 128;
    const int m0 = blockIdx.y * 64;
    const int tid = threadIdx.x;
    const int wid = tid >> 5, wr = wid >> 2, wc = wid & 3;

    wmma::fragment<wmma::accumulator, 16, 16, 8, float> acc[2][2];
#pragma unroll
    for (int i = 0; i < 2; i++)
#pragma unroll
        for (int j = 0; j < 2; j++) wmma::fill_fragment(acc[i][j], 0.0f);

    for (int k0 = 0; k0 < DIM; k0 += 32) {
#pragma unroll
        for (int i = 0; i < 2; i++) {
            int idx = tid + i * 256;
            int m = idx >> 3, k4 = (idx & 7) << 2;
            *(float4*)(As + m * 40 + k4) =
                *(const float4*)(g_att + (size_t)(m0 + m) * DIM + k0 + k4);
        }
#pragma unroll
        for (int i = 0; i < 4; i++) {
            int idx = tid + i * 256;
            int kk = idx >> 5, n4 = (idx & 31) << 2;
            *(float4*)(Bs + kk * 136 + n4) =
                *(const float4*)(Wo + (size_t)(k0 + kk) * DIM + n0 + n4);
        }
        __syncthreads();
        mma_rowB<40, 136>(As, Bs, acc, wr, wc);
        __syncthreads();
    }
#pragma unroll
    for (int i = 0; i < 2; i++)
#pragma unroll
        for (int j = 0; j < 2; j++)
            wmma::store_matrix_sync(
                out + (size_t)(m0 + wr * 32 + i * 16) * DIM + n0 + wc * 32 + j * 16,
                acc[i][j], DIM, wmma::mem_row_major);
}

// ---------------- kernel 7: add output bias ------------------------------------
__global__ void bias_kernel(float* __restrict__ out, const float* __restrict__ bo)
{
    int t = blockIdx.x * 256 + threadIdx.x;
    int i4 = t * 4;
    int n = i4 & (DIM - 1);
    float4 v = *(const float4*)(out + i4);
    float4 bb = *(const float4*)(bo + n);
    v.x += bb.x; v.y += bb.y; v.z += bb.z; v.w += bb.w;
    *(float4*)(out + i4) = v;
}

// ---------------- launch ---------------------------------------------------------
extern "C" void kernel_launch(void* const* d_in, const int* in_sizes, int n_in,
                              void* d_out, int out_size)
{
    const float* x  = (const float*)d_in[0];
    const float* kc = (const float*)d_in[1];
    const float* vc = (const float*)d_in[2];
    const float* Wq = (const float*)d_in[3];  const float* bq = (const float*)d_in[4];
    const float* Wk = (const float*)d_in[5];  const float* bk = (const float*)d_in[6];
    const float* Wv = (const float*)d_in[7];  const float* bv = (const float*)d_in[8];
    const float* Wo = (const float*)d_in[9];  const float* bo = (const float*)d_in[10];
    float* out = (float*)d_out;

    qkv_kernel<<<dim3(48, 2), 256>>>(x, Wq, Wk, Wv);
    scores_kernel<<<dim3(32, NBG), 256>>>(kc, bq, bk);
    softmax_kernel<<<NBG * 64, 256>>>();
    pv_kernel<<<dim3(PV_SPLITS, NBG), 256>>>(vc, bv);
    pv_reduce_kernel<<<512, 256>>>();
    o_kernel<<<dim3(32, 2), 256>>>(Wo, out);
    bias_kernel<<<512, 256>>>(out, bo);
}